// round 4
// baseline (speedup 1.0000x reference)
#include <cuda_runtime.h>
#include <cuda_bf16.h>
#include <math.h>

// Shapes (fixed by the problem)
#define NQ   10
#define NL   4
#define NG   (NL * NQ)   // 40 single-qubit gates
#define NDIM 1024        // 2^NQ amplitudes
#define FFN  4096
#define EDIM 1024
#define NTOK 16384       // B*T
#define GRID 128         // blocks; 1 block/SM (64 regs x 1024 thr) -> all resident

// Persistent flags/scratch (self-resetting each launch)
__device__ float g_z[16];
__device__ __align__(16) float g_y[EDIM];
__device__ volatile int g_zflag  = 0;
__device__ volatile int g_ycount = 0;
__device__ int g_done = 0;

__device__ __forceinline__ float2 cmul(float2 a, float2 b) {
    return make_float2(fmaf(a.x, b.x, -a.y * b.y), fmaf(a.x, b.y, a.y * b.x));
}
__device__ __forceinline__ float2 cfma2(float2 u, float2 a, float2 v, float2 b) {
    float re = fmaf(u.x, a.x, -u.y * a.y);
    re = fmaf(v.x, b.x, re);
    re = fmaf(-v.y, b.y, re);
    float im = fmaf(u.x, a.y, u.y * a.x);
    im = fmaf(v.x, b.y, im);
    im = fmaf(v.y, b.x, im);
    return make_float2(re, im);
}

__device__ __forceinline__ void l2_prefetch(const void* p) {
    asm volatile("prefetch.global.L2 [%0];" :: "l"(p));
}

// padded smem index (kills transpose bank conflicts)
#define SIDX(i) ((i) + ((i) >> 5))

__global__ void __launch_bounds__(1024, 1)
fused_kernel(const float* __restrict__ params,
             const float* __restrict__ W1,
             const float* __restrict__ b1,
             const float* __restrict__ W2,
             const float* __restrict__ b2,
             float* __restrict__ out) {
    __shared__ float2 U[NG][2];
    __shared__ float2 st[2][NDIM + 32];
    __shared__ float  wsum[32][NQ];
    __shared__ float  h_s[FFN];
    __shared__ float  red[32];

    const int t    = threadIdx.x;
    const int b    = blockIdx.x;
    const int lane = t & 31;
    const int warp = t >> 5;

    if (b == 0) {
        // ================= circuit (block 0 only) =================
        if (t < NG) {
            const float t0 = params[t * 3 + 0];
            const float t1 = params[t * 3 + 1];
            const float t2 = params[t * 3 + 2];
            float cx, sx, cy, sy, cz, sz;
            sincosf(0.5f * t0, &sx, &cx);
            sincosf(0.5f * t1, &sy, &cy);
            sincosf(0.5f * t2, &sz, &cz);
            const float2 m00 = make_float2( cy * cx,  sy * sx);
            const float2 m01 = make_float2(-sy * cx, -cy * sx);
            const float2 ezm = make_float2(cz, -sz);
            U[t][0] = cmul(ezm, m00);
            U[t][1] = cmul(ezm, m01);
        }
        const int Pt = ((t & 31) << 5) | (t >> 5);
        int Ct = t;
        #pragma unroll
        for (int e = NQ - 1; e >= 0; e--) {
            const int c  = (e < NQ - 1) ? e : NQ - 1;
            const int tq = (e < NQ - 1) ? e + 1 : 0;
            const int cm = 1 << (NQ - 1 - c);
            const int tm = 1 << (NQ - 1 - tq);
            Ct ^= (Ct & cm) ? tm : 0;
        }
        float sgn[5];
        #pragma unroll
        for (int k = 0; k < 5; k++) sgn[k] = (t & (16 >> k)) ? -1.0f : 1.0f;

        float2 a = make_float2(t == 0 ? 1.0f : 0.0f, 0.0f);
        __syncthreads();

        int cur = 0;
        #pragma unroll 1
        for (int l = 0; l < NL; l++) {
            #pragma unroll
            for (int k = 0; k < 5; k++) {
                const int g = l * NQ + 5 + k;
                float2 u0 = U[g][0];
                float2 u1 = U[g][1];
                const float s = sgn[k];
                u0.y *= s; u1.x *= s;
                const int m = 16 >> k;
                float2 bb;
                bb.x = __shfl_xor_sync(0xffffffffu, a.x, m);
                bb.y = __shfl_xor_sync(0xffffffffu, a.y, m);
                a = cfma2(u0, a, u1, bb);
            }
            st[cur][SIDX(t)] = a;
            __syncthreads();
            a = st[cur][SIDX(Pt)];
            cur ^= 1;
            #pragma unroll
            for (int k = 0; k < 5; k++) {
                const int g = l * NQ + k;
                float2 u0 = U[g][0];
                float2 u1 = U[g][1];
                const float s = sgn[k];
                u0.y *= s; u1.x *= s;
                const int m = 16 >> k;
                float2 bb;
                bb.x = __shfl_xor_sync(0xffffffffu, a.x, m);
                bb.y = __shfl_xor_sync(0xffffffffu, a.y, m);
                a = cfma2(u0, a, u1, bb);
            }
            st[cur][SIDX(Pt)] = a;
            __syncthreads();
            a = st[cur][SIDX(Ct)];
            cur ^= 1;
        }

        // <Z_q>
        const float p = fmaf(a.x, a.x, a.y * a.y);
        #pragma unroll
        for (int q = 0; q < NQ; q++) {
            const int mask = 1 << (NQ - 1 - q);
            float v = (t & mask) ? p : 0.0f;
            #pragma unroll
            for (int o = 16; o > 0; o >>= 1) v += __shfl_xor_sync(0xffffffffu, v, o);
            if (lane == 0) wsum[warp][q] = v;
        }
        __syncthreads();
        if (t < NQ) {
            float s = 0.0f;
            #pragma unroll
            for (int w = 0; w < 32; w++) s += wsum[w][t];
            g_z[t] = 1.0f - 2.0f * s;
            __threadfence();
        }
        __syncthreads();
        if (t == 0) g_zflag = 1;   // release (fenced above)
    } else {
        // ======= blocks 1..127: prefetch L2, then wait for z =======
        // own W2 slice: rows [8b, 8b+8) = 128KB = 1024 lines
        {
            const char* base = (const char*)(W2 + (size_t)b * 8 * FFN);
            l2_prefetch(base + (size_t)t * 128);
        }
        if (b == 1) {
            // block 0's W2 slice
            const char* base0 = (const char*)W2;
            l2_prefetch(base0 + (size_t)t * 128);
            // W1: 160KB = 1280 lines
            const char* w1b = (const char*)W1;
            l2_prefetch(w1b + (size_t)t * 128);
            if (t < 256) l2_prefetch(w1b + (size_t)(1024 + t) * 128);
            // b1 (16KB = 128 lines), b2 (4KB = 32 lines)
            if (t < 128) l2_prefetch((const char*)b1 + (size_t)t * 128);
            if (t < 32)  l2_prefetch((const char*)b2 + (size_t)t * 128);
        }
        if (t == 0) {
            while (g_zflag == 0) __nanosleep(64);
        }
        __syncthreads();
        __threadfence();   // acquire
    }

    // ================= all blocks: h = relu(W1 z + b1) =================
    float z[NQ];
    #pragma unroll
    for (int q = 0; q < NQ; q++) z[q] = g_z[q];

    {
        const float4* __restrict__ Wv = ((const float4*)W1) + (size_t)t * 10;
        float f[20];
        float acc[4];

        float4 v0 = Wv[0], v1 = Wv[1], v2 = Wv[2], v3 = Wv[3], v4 = Wv[4];
        f[0]=v0.x; f[1]=v0.y; f[2]=v0.z; f[3]=v0.w;
        f[4]=v1.x; f[5]=v1.y; f[6]=v1.z; f[7]=v1.w;
        f[8]=v2.x; f[9]=v2.y; f[10]=v2.z; f[11]=v2.w;
        f[12]=v3.x; f[13]=v3.y; f[14]=v3.z; f[15]=v3.w;
        f[16]=v4.x; f[17]=v4.y; f[18]=v4.z; f[19]=v4.w;
        acc[0] = 0.0f; acc[1] = 0.0f;
        #pragma unroll
        for (int q = 0; q < NQ; q++) acc[0] = fmaf(f[q],      z[q], acc[0]);
        #pragma unroll
        for (int q = 0; q < NQ; q++) acc[1] = fmaf(f[10 + q], z[q], acc[1]);

        v0 = Wv[5]; v1 = Wv[6]; v2 = Wv[7]; v3 = Wv[8]; v4 = Wv[9];
        f[0]=v0.x; f[1]=v0.y; f[2]=v0.z; f[3]=v0.w;
        f[4]=v1.x; f[5]=v1.y; f[6]=v1.z; f[7]=v1.w;
        f[8]=v2.x; f[9]=v2.y; f[10]=v2.z; f[11]=v2.w;
        f[12]=v3.x; f[13]=v3.y; f[14]=v3.z; f[15]=v3.w;
        f[16]=v4.x; f[17]=v4.y; f[18]=v4.z; f[19]=v4.w;
        acc[2] = 0.0f; acc[3] = 0.0f;
        #pragma unroll
        for (int q = 0; q < NQ; q++) acc[2] = fmaf(f[q],      z[q], acc[2]);
        #pragma unroll
        for (int q = 0; q < NQ; q++) acc[3] = fmaf(f[10 + q], z[q], acc[3]);

        const float4 bb = ((const float4*)b1)[t];
        float4 hv;
        hv.x = fmaxf(acc[0] + bb.x, 0.0f);
        hv.y = fmaxf(acc[1] + bb.y, 0.0f);
        hv.z = fmaxf(acc[2] + bb.z, 0.0f);
        hv.w = fmaxf(acc[3] + bb.w, 0.0f);
        ((float4*)h_s)[t] = hv;
    }
    __syncthreads();

    // ============ y slice: block b computes y[8b .. 8b+8) ============
    {
        const int grp = t >> 7;          // 0..7
        const int j   = t & 127;
        const int e   = b * 8 + grp;
        const float4* __restrict__ w4 = (const float4*)(W2 + (size_t)e * FFN);
        const float4* __restrict__ h4 = (const float4*)h_s;
        float acc = 0.0f;
        #pragma unroll
        for (int m = 0; m < 8; m++) {
            const int idx = j + 128 * m;
            const float4 w = w4[idx];
            const float4 h = h4[idx];
            acc += w.x * h.x + w.y * h.y + w.z * h.z + w.w * h.w;
        }
        #pragma unroll
        for (int o = 16; o > 0; o >>= 1) acc += __shfl_down_sync(0xffffffffu, acc, o);
        if (lane == 0) red[warp] = acc;
        __syncthreads();
        if (j == 0) {
            const float v = red[grp * 4 + 0] + red[grp * 4 + 1]
                          + red[grp * 4 + 2] + red[grp * 4 + 3];
            g_y[e] = v + b2[e];
            __threadfence();
        }
        __syncthreads();
        if (t == 0) atomicAdd((int*)&g_ycount, 1);
    }

    // wait for all 128 y slices
    if (t == 0) {
        while (g_ycount < GRID) __nanosleep(64);
    }
    __syncthreads();
    __threadfence();

    // ============ fill: block b stores rows [128b, 128b+128) ============
    {
        const float4 yv = ((const float4*)g_y)[t & 255];
        float4* __restrict__ o4 = (float4*)out;
        const int r0 = b * 128 + (t >> 8);      // t>>8 in 0..3
        #pragma unroll 8
        for (int i = 0; i < 32; i++) {
            o4[(size_t)(r0 + i * 4) * 256 + (t & 255)] = yv;
        }
    }

    // ============ self-reset for next graph replay ============
    __syncthreads();
    if (t == 0) {
        const int d = atomicAdd(&g_done, 1);
        if (d == GRID - 1) {
            g_zflag  = 0;
            g_ycount = 0;
            __threadfence();
            g_done = 0;
        }
    }
}

// ---------------------------------------------------------------------------
// inputs: 0=x, 1=W_in, 2=b_in, 3=params, 4=W1, 5=b1, 6=W2, 7=b2
// x / W_in / b_in are dead in the reference.
// ---------------------------------------------------------------------------
extern "C" void kernel_launch(void* const* d_in, const int* in_sizes, int n_in,
                              void* d_out, int out_size) {
    const float* params = (const float*)d_in[3];
    const float* W1     = (const float*)d_in[4];
    const float* b1     = (const float*)d_in[5];
    const float* W2     = (const float*)d_in[6];
    const float* b2     = (const float*)d_in[7];
    float* out = (float*)d_out;

    fused_kernel<<<GRID, 1024>>>(params, W1, b1, W2, b2, out);
}